// round 15
// baseline (speedup 1.0000x reference)
#include <cuda_runtime.h>
#include <cstdint>

// Problem constants
#define NMAX 50000
#define EMAX 1000000
#define RNUM 8
#define BNUM 30
#define JTOT 576            // 8*64 relation cols + 64 self-loop cols
#define NSEG (NMAX * RNUM)  // 400000 (dst,relation) segments
#define SCHUNK 512
#define NBLK2 782           // ceil(400000/512)
#define NPAD2 (NBLK2 * SCHUNK)   // 400384

// double-buffered gemm dynamic smem: 2*(32*132 + 32*64) floats = 50176 B
#define GEMM_SMEM 50176

// ---------------- static device scratch ----------------
__device__ float g_Wtmp[JTOT * 64];              // Wcat [kk][o]
__device__ float g_Wcat2[JTOT * 64];             // Wcat @ W2 [kk][o]
__device__ float g_bias12[64];                   // bias1 @ W2
__device__ float g_z[(size_t)NMAX * JTOT];       // per-dst relation sums | self x
__device__ float g_g[(size_t)NMAX * 64];         // s * (z@Wcat2 + bias12)
__device__ int   g_deg_out[NMAX];
__device__ int   g_deg[NPAD2];                   // per-(dst,rel) counts, zero-padded
__device__ int   g_cursor[NSEG];
__device__ int   g_rowoff[NSEG + 1];
__device__ int   g_bsum[NBLK2];
__device__ int   g_boff[NBLK2];
__device__ int   g_csr[EMAX];                    // bare src index

// ---------------- f32x2 packed-FMA helpers ----------------
typedef unsigned long long ull;
__device__ __forceinline__ ull pack2(float lo, float hi) {
    ull r; asm("mov.b64 %0,{%1,%2};" : "=l"(r) : "f"(lo), "f"(hi)); return r;
}
__device__ __forceinline__ void unpack2(ull v, float& lo, float& hi) {
    asm("mov.b64 {%0,%1},%2;" : "=f"(lo), "=f"(hi) : "l"(v));
}
__device__ __forceinline__ void ffma2(ull& d, ull a, ull b) {
    asm("fma.rn.f32x2 %0,%1,%2,%0;" : "+l"(d) : "l"(a), "l"(b));
}

// ---------------- K0: zero counters ----------------
__global__ void zero_kernel(int n) {
    int i = blockIdx.x * blockDim.x + threadIdx.x;
    if (i < NPAD2) g_deg[i] = 0;
    if (i < NSEG) g_cursor[i] = 0;
    if (i < n) g_deg_out[i] = 0;
    if (i == 0) g_rowoff[0] = 0;
}

// ---------------- K1: Wcat (relation weights | loop weights) ----------------
__global__ void wcat_kernel(const float* __restrict__ basis,
                            const float* __restrict__ comp,
                            const float* __restrict__ loopw) {
    int idx = blockIdx.x * blockDim.x + threadIdx.x;
    if (idx >= JTOT * 64) return;
    int o = idx & 63;
    int kk = idx >> 6;
    if (kk < RNUM * 64) {
        int r = kk >> 6, i = kk & 63;
        float s = 0.f;
#pragma unroll
        for (int b = 0; b < BNUM; b++)
            s += comp[r * BNUM + b] * basis[(b * 64 + i) * 64 + o];
        g_Wtmp[kk * 64 + o] = s;
    } else {
        int i = kk - RNUM * 64;
        g_Wtmp[kk * 64 + o] = loopw[i * 64 + o];
    }
}

// ---------------- K1b: Wcat2 = Wcat @ W2, bias12 = bias1 @ W2 ----------------
__global__ void wcat2_kernel(const float* __restrict__ w2,
                             const float* __restrict__ bias1) {
    int idx = blockIdx.x * blockDim.x + threadIdx.x;
    if (idx >= JTOT * 64) return;
    int o = idx & 63;
    int kk = idx >> 6;
    float s = 0.f;
#pragma unroll 8
    for (int k = 0; k < 64; k++)
        s += g_Wtmp[kk * 64 + k] * w2[k * 64 + o];
    g_Wcat2[kk * 64 + o] = s;
    if (idx < 64) {
        float b = 0.f;
#pragma unroll 8
        for (int k = 0; k < 64; k++)
            b += bias1[k] * w2[k * 64 + idx];
        g_bias12[idx] = b;
    }
}

// ---------------- K2: counts per (dst,rel) segment + out-degree ----------------
__global__ void deg_kernel(const int* __restrict__ ei,
                           const int* __restrict__ et, int e) {
    int i = blockIdx.x * blockDim.x + threadIdx.x;
    if (i < e) {
        atomicAdd(&g_deg_out[ei[i]], 1);
        atomicAdd(&g_deg[ei[e + i] * RNUM + et[i]], 1);
    }
}

// ---------------- K3a: per-block sums ----------------
__global__ void scan1_kernel() {
    __shared__ int ws[8];
    int b = blockIdx.x, tid = threadIdx.x, lane = tid & 31, wid = tid >> 5;
    int2 v = *(const int2*)&g_deg[b * SCHUNK + tid * 2];
    int s = v.x + v.y;
#pragma unroll
    for (int off = 16; off >= 1; off >>= 1)
        s += __shfl_down_sync(0xFFFFFFFFu, s, off);
    if (lane == 0) ws[wid] = s;
    __syncthreads();
    if (tid == 0) {
        int t = 0;
#pragma unroll
        for (int j = 0; j < 8; j++) t += ws[j];
        g_bsum[b] = t;
    }
}

// ---------------- K3b: exclusive scan of block sums ----------------
__global__ void scan2_kernel() {
    __shared__ int wsum[32];
    int tid = threadIdx.x, lane = tid & 31, wid = tid >> 5;
    int v = (tid < NBLK2) ? g_bsum[tid] : 0;
    int sc = v;
#pragma unroll
    for (int off = 1; off < 32; off <<= 1) {
        int t = __shfl_up_sync(0xFFFFFFFFu, sc, off);
        if (lane >= off) sc += t;
    }
    if (lane == 31) wsum[wid] = sc;
    __syncthreads();
    if (wid == 0) {
        int w = wsum[lane];
        int s2 = w;
#pragma unroll
        for (int off = 1; off < 32; off <<= 1) {
            int t = __shfl_up_sync(0xFFFFFFFFu, s2, off);
            if (lane >= off) s2 += t;
        }
        wsum[lane] = s2 - w;
    }
    __syncthreads();
    if (tid < NBLK2) g_boff[tid] = sc - v + wsum[wid];
}

// ---------------- K3c: per-block scan + global offset -> rowoff ----------------
__global__ void scan3_kernel() {
    __shared__ int ws[8];
    __shared__ int wx[8];
    int b = blockIdx.x, tid = threadIdx.x, lane = tid & 31, wid = tid >> 5;
    int i0 = b * SCHUNK + tid * 2;
    int2 v = *(const int2*)&g_deg[i0];
    int ps = v.x + v.y;
    int sc = ps;
#pragma unroll
    for (int off = 1; off < 32; off <<= 1) {
        int t = __shfl_up_sync(0xFFFFFFFFu, sc, off);
        if (lane >= off) sc += t;
    }
    if (lane == 31) ws[wid] = sc;
    __syncthreads();
    if (tid == 0) {
        int run = 0;
#pragma unroll
        for (int j = 0; j < 8; j++) { wx[j] = run; run += ws[j]; }
    }
    __syncthreads();
    int excl = (sc - ps) + wx[wid] + g_boff[b];
    int r1 = excl + v.x;
    int r2 = r1 + v.y;
    if (i0 < NSEG)     g_rowoff[i0 + 1] = r1;
    if (i0 + 1 < NSEG) g_rowoff[i0 + 2] = r2;
}

// ---------------- K4: fill CSR (sorted by (dst, rel)) ----------------
__global__ void fill_kernel(const int* __restrict__ ei,
                            const int* __restrict__ et, int e) {
    int i = blockIdx.x * blockDim.x + threadIdx.x;
    if (i < e) {
        int seg = ei[e + i] * RNUM + et[i];
        int pos = g_rowoff[seg] + atomicAdd(&g_cursor[seg], 1);
        g_csr[pos] = ei[i];
    }
}

// ---------------- K5: aggregate x[src] per (dst,rel) segment -> z (round-13 version) ----------------
__global__ void aggz_kernel(const float* __restrict__ x, int n) {
    int gw   = (blockIdx.x * blockDim.x + threadIdx.x) >> 5;
    int lane = threadIdx.x & 31;
    if (gw >= n) return;
    float* zr = &g_z[(size_t)gw * JTOT];
    int base = gw * RNUM;
    int beg = g_rowoff[base];
#pragma unroll 1
    for (int r = 0; r < RNUM; r++) {
        int end = g_rowoff[base + r + 1];
        float a0 = 0.f, a1 = 0.f;
        int e = beg;
        for (; e + 1 < end; e += 2) {
            int p0 = g_csr[e], p1 = g_csr[e + 1];
            const float* s0 = &x[(size_t)p0 * 64];
            const float* s1 = &x[(size_t)p1 * 64];
            float v00 = s0[lane],      v10 = s1[lane];
            float v01 = s0[lane + 32], v11 = s1[lane + 32];
            a0 += v00 + v10;
            a1 += v01 + v11;
        }
        if (e < end) {
            const float* s0 = &x[(size_t)g_csr[e] * 64];
            a0 += s0[lane];
            a1 += s0[lane + 32];
        }
        zr[r * 64 + lane]      = a0;
        zr[r * 64 + lane + 32] = a1;
        beg = end;
    }
    zr[512 + lane]      = x[(size_t)gw * 64 + lane];
    zr[512 + lane + 32] = x[(size_t)gw * 64 + lane + 32];
}

// ---------------- K6: GEMM (double-buffered): g = rsqrt(deg_out)*(z @ Wcat2 + bias12) ----------------
__global__ __launch_bounds__(256) void gemm_kernel(int M) {
    extern __shared__ float dynsm[];
    float* A0 = dynsm;                 // [32][132]
    float* A1 = A0 + 32 * 132;
    float* B0 = A1 + 32 * 132;         // [32][64]
    float* B1 = B0 + 32 * 64;

    int tid = threadIdx.x;
    int tx = tid & 15, ty = tid >> 4;
    int mBase = blockIdx.x * 128;
    int rowL = tid >> 1, half = tid & 1;
    int gr = mBase + rowL;

    auto loadChunk = [&](int c, int buf) {
        float* sA = buf ? A1 : A0;
        float* sB = buf ? B1 : B0;
        int k0 = c * 32;
#pragma unroll
        for (int q = 0; q < 4; q++) {
            int kk = half * 16 + q * 4;
            float4 v = make_float4(0.f, 0.f, 0.f, 0.f);
            if (gr < M) v = *(const float4*)&g_z[(size_t)gr * JTOT + k0 + kk];
            sA[kk * 132 + rowL]       = v.x;
            sA[(kk + 1) * 132 + rowL] = v.y;
            sA[(kk + 2) * 132 + rowL] = v.z;
            sA[(kk + 3) * 132 + rowL] = v.w;
        }
        int f = tid * 8, kr = f >> 6, cc = f & 63;
        *(float4*)&sB[kr * 64 + cc]     = *(const float4*)&g_Wcat2[(size_t)(k0 + kr) * 64 + cc];
        *(float4*)&sB[kr * 64 + cc + 4] = *(const float4*)&g_Wcat2[(size_t)(k0 + kr) * 64 + cc + 4];
    };

    ull acc[4][4] = {};
    loadChunk(0, 0);
    __syncthreads();
#pragma unroll 1
    for (int c = 0; c < JTOT / 32; c++) {
        int buf = c & 1;
        if (c + 1 < JTOT / 32) loadChunk(c + 1, buf ^ 1);   // overlap next loads with compute
        const float* sA = buf ? A1 : A0;
        const float* sB = buf ? B1 : B0;
#pragma unroll
        for (int k = 0; k < 32; k++) {
            float4 b = *(const float4*)&sB[k * 64 + tx * 4];
            ull bd0 = pack2(b.x, b.x), bd1 = pack2(b.y, b.y);
            ull bd2 = pack2(b.z, b.z), bd3 = pack2(b.w, b.w);
#pragma unroll
            for (int i = 0; i < 4; i++) {
                ull a = *(const ull*)&sA[k * 132 + ty * 8 + 2 * i];
                ffma2(acc[i][0], a, bd0);
                ffma2(acc[i][1], a, bd1);
                ffma2(acc[i][2], a, bd2);
                ffma2(acc[i][3], a, bd3);
            }
        }
        __syncthreads();
    }
    float4 bv = *(const float4*)&g_bias12[tx * 4];
#pragma unroll
    for (int i = 0; i < 4; i++) {
        float lo[4], hi[4];
#pragma unroll
        for (int j = 0; j < 4; j++) unpack2(acc[i][j], lo[j], hi[j]);
        int g0 = mBase + ty * 8 + 2 * i, g1 = g0 + 1;
        if (g0 < M) {
            float s = rsqrtf((float)max(g_deg_out[g0], 1));
            *(float4*)&g_g[(size_t)g0 * 64 + tx * 4] =
                make_float4((lo[0] + bv.x) * s, (lo[1] + bv.y) * s,
                            (lo[2] + bv.z) * s, (lo[3] + bv.w) * s);
        }
        if (g1 < M) {
            float s = rsqrtf((float)max(g_deg_out[g1], 1));
            *(float4*)&g_g[(size_t)g1 * 64 + tx * 4] =
                make_float4((hi[0] + bv.x) * s, (hi[1] + bv.y) * s,
                            (hi[2] + bv.z) * s, (hi[3] + bv.w) * s);
        }
    }
}

// ---------------- K7: out = rsqrt(deg_in)*sum g[src] + bias2  (round-13 version) ----------------
__global__ void agg3_kernel(const float* __restrict__ bias2,
                            float* __restrict__ out, int n) {
    int gw   = (blockIdx.x * blockDim.x + threadIdx.x) >> 5;
    int lane = threadIdx.x & 31;
    if (gw >= n) return;
    int beg = g_rowoff[gw * RNUM], end = g_rowoff[gw * RNUM + RNUM];

    float a0 = 0.f, a1 = 0.f;
    int e = beg;
    for (; e + 3 < end; e += 4) {
        int p0 = g_csr[e], p1 = g_csr[e + 1], p2 = g_csr[e + 2], p3 = g_csr[e + 3];
        const float* h0 = &g_g[(size_t)p0 * 64];
        const float* h1 = &g_g[(size_t)p1 * 64];
        const float* h2 = &g_g[(size_t)p2 * 64];
        const float* h3 = &g_g[(size_t)p3 * 64];
        float v0 = h0[lane], v1 = h1[lane], v2 = h2[lane], v3 = h3[lane];
        float u0 = h0[lane + 32], u1 = h1[lane + 32], u2 = h2[lane + 32], u3 = h3[lane + 32];
        a0 += (v0 + v1) + (v2 + v3);
        a1 += (u0 + u1) + (u2 + u3);
    }
    for (; e < end; e++) {
        const float* h = &g_g[(size_t)g_csr[e] * 64];
        a0 += h[lane];
        a1 += h[lane + 32];
    }
    float sc = rsqrtf((float)max(end - beg, 1));
    out[(size_t)gw * 64 + lane]      = a0 * sc + bias2[lane];
    out[(size_t)gw * 64 + lane + 32] = a1 * sc + bias2[lane + 32];
}

// ---------------- launch ----------------
extern "C" void kernel_launch(void* const* d_in, const int* in_sizes, int n_in,
                              void* d_out, int out_size) {
    const float* x     = (const float*)d_in[0];
    const int*   ei    = (const int*)d_in[1];   // int32 (JAX x64 disabled)
    const int*   et    = (const int*)d_in[3];   // int32
    const float* basis = (const float*)d_in[4];
    const float* comp  = (const float*)d_in[5];
    const float* loopw = (const float*)d_in[6];
    const float* bias1 = (const float*)d_in[7];
    const float* w2    = (const float*)d_in[8];
    const float* bias2 = (const float*)d_in[9];
    float* out = (float*)d_out;

    int n = in_sizes[0] / 64;    // 50000
    int e = in_sizes[1] / 2;     // 1000000

    static int smem_set = 0;
    if (!smem_set) {
        cudaFuncSetAttribute(gemm_kernel,
                             cudaFuncAttributeMaxDynamicSharedMemorySize, GEMM_SMEM);
        smem_set = 1;
    }

    zero_kernel<<<(NPAD2 + 255) / 256, 256>>>(n);
    wcat_kernel<<<(JTOT * 64 + 255) / 256, 256>>>(basis, comp, loopw);
    wcat2_kernel<<<(JTOT * 64 + 255) / 256, 256>>>(w2, bias1);
    deg_kernel<<<(e + 255) / 256, 256>>>(ei, et, e);
    scan1_kernel<<<NBLK2, 256>>>();
    scan2_kernel<<<1, 1024>>>();
    scan3_kernel<<<NBLK2, 256>>>();
    fill_kernel<<<(e + 255) / 256, 256>>>(ei, et, e);

    aggz_kernel<<<(n * 32 + 255) / 256, 256>>>(x, n);
    gemm_kernel<<<(n + 127) / 128, 256, GEMM_SMEM>>>(n);
    agg3_kernel<<<(n * 32 + 255) / 256, 256>>>(bias2, out, n);
}